// round 15
// baseline (speedup 1.0000x reference)
#include <cuda_runtime.h>
#include <cuda_fp16.h>
#include <math.h>

#define C_DIM 256
#define NROI  512
#define NBIN  49

// NHWC fp16 scratch, 4 levels (element offsets):
// lvl0 base 0 (2*256*256*256), lvl1 base 33554432, lvl2 base 41943040, lvl3 base 44040192
__device__ __half g_nhwc[44564480];

// Per-tile "needed" flags.
// lvl0: 16-px tiles -> 4096/batch, [0, 8192)
// lvl1: 16-px tiles -> 1024/batch, [8192, 10240)
// lvl2: 64-px tiles -> 64/batch,   [10240, 10368)
// lvl3: 64-px tiles -> 16/batch,   [10368, 10400)
// Zero-initialized at load; re-zeroed by k_gather's epilogue each call.
#define NFLAGS 10400
__device__ unsigned char g_flags[NFLAGS];

// Marker-completion counter (zero-init; reset by k_gather epilogue).
__device__ int g_mark_done;

#define MARK_BLOCKS 512
#define S16_LVL0 32768           // 2b * 4c * 4096
#define S16_LVL1 8192            // 2b * 4c * 1024
#define S64_BLOCKS 640           // lvl2 512 + lvl3 128
#define T_ALL (MARK_BLOCKS + S16_LVL0 + S16_LVL1 + S64_BLOCKS)   // 42112

__device__ __forceinline__ void roi_level(float bx1, float by1, float bx2, float by2,
                                          int& lvl, int& H, float& scale) {
    const float size = sqrtf((bx2 - bx1) * (by2 - by1));
    int l = (int)floorf(4.0f + log2f(size / 224.0f + 1e-8f));
    lvl = max(2, min(5, l)) - 2;
    H = 256 >> lvl;
    scale = 0.25f / (float)(1 << lvl);
}

// -------------------------------------------------------------------------
// Fused mark + transpose, ONE launch.
// Blocks [0,512): markers (one ROI each; wave-1 guaranteed since 512 < wave).
// Blocks [512, 512+40960): 16-px-tile transpose (lvl0 then lvl1).
// Blocks [last 640): 64-px-tile transpose (lvl2, lvl3).
// Non-marker blocks spin (~1-2us, wave-1 only) until all markers signal.
// -------------------------------------------------------------------------
__global__ __launch_bounds__(256) void k_fused(const float* __restrict__ p0,
                                               const float* __restrict__ p1,
                                               const float* __restrict__ p2,
                                               const float* __restrict__ p3,
                                               const float* __restrict__ boxes) {
    __shared__ float smem_tile[64 * 65];   // union: 16hw path uses 64*17
    const int t = threadIdx.x;
    int bid = blockIdx.x;

    // ===================== markers (blocks 0..511) =====================
    if (bid < MARK_BLOCKS) {
        const int roi = bid;
        const int b   = roi >> 8;
        const float bx1 = __ldg(boxes + roi * 4 + 0);
        const float by1 = __ldg(boxes + roi * 4 + 1);
        const float bx2 = __ldg(boxes + roi * 4 + 2);
        const float by2 = __ldg(boxes + roi * 4 + 3);

        int lvl, H; float scale;
        roi_level(bx1, by1, bx2, by2, lvl, H, scale);

        const float x1s = bx1 * scale - 0.5f;
        const float y1s = by1 * scale - 0.5f;
        const float x2s = bx2 * scale - 0.5f;
        const float y2s = by2 * scale - 0.5f;

        const float Hm1 = (float)(H - 1);
        const int xa = (int)floorf(fminf(fmaxf(x1s, 0.0f), Hm1));
        const int xb = min((int)floorf(fminf(fmaxf(x2s, 0.0f), Hm1)) + 1, H - 1);
        const int ya = (int)floorf(fminf(fmaxf(y1s, 0.0f), Hm1));
        const int yb = min((int)floorf(fminf(fmaxf(y2s, 0.0f), Hm1)) + 1, H - 1);

        const int fbase   = (lvl == 0) ? 0 : (lvl == 1) ? 8192 : (lvl == 2) ? 10240 : 10368;
        const int tilesPB = (lvl == 0) ? 4096 : (lvl == 1) ? 1024 : (lvl == 2) ? 64 : 16;
        const int sh      = (lvl <= 1) ? 4 : 6;
        unsigned char* fl = g_flags + fbase + b * tilesPB;

        for (int y = ya + t; y <= yb; y += 256) {
            const int t0 = (y * H + xa) >> sh;
            const int t1 = (y * H + xb) >> sh;
            for (int tt = t0; tt <= t1; tt++) fl[tt] = 1;
        }
        __threadfence();            // publish flag stores
        __syncthreads();
        if (t == 0) atomicAdd(&g_mark_done, 1);   // release
        return;
    }

    // ===================== transposers: wait for markers =====================
    if (t == 0) {
        while (*(volatile int*)&g_mark_done < MARK_BLOCKS) __nanosleep(64);
        __threadfence();            // acquire
    }
    __syncthreads();

    bid -= MARK_BLOCKS;

    if (bid < S16_LVL0 + S16_LVL1) {
        // ---------------- 16-px-tile path (lvl0, lvl1) ----------------
        int lvl, HW, hwTile, cTile, b, fbase;
        const float* __restrict__ in;
        size_t base;
        if (bid < S16_LVL0) {
            lvl = 0; in = p0; base = 0ul; fbase = 0; HW = 65536;
            hwTile = bid & 4095; cTile = (bid >> 12) & 3; b = bid >> 14;
        } else {
            bid -= S16_LVL0;
            lvl = 1; in = p1; base = 33554432ul; fbase = 8192; HW = 16384;
            hwTile = bid & 1023; cTile = (bid >> 10) & 3; b = bid >> 12;
        }
        const int tilesPB = (lvl == 0) ? 4096 : 1024;
        if (__ldcg(&g_flags[fbase + b * tilesPB + hwTile]) == 0) return;

        float (*tile)[17] = (float(*)[17])smem_tile;
        const int hw0 = hwTile << 4;
        const int c0  = cTile << 6;

        const int c = t >> 2;
        const int g = t & 3;

        const float* __restrict__ ip =
            in + (size_t)b * C_DIM * HW + (size_t)(c0 + c) * HW + hw0 + 4 * g;
        const float4 v = __ldcs((const float4*)ip);
        tile[c][4 * g + 0] = v.x;
        tile[c][4 * g + 1] = v.y;
        tile[c][4 * g + 2] = v.z;
        tile[c][4 * g + 3] = v.w;
        __syncthreads();

        __half* __restrict__ op =
            g_nhwc + base + (size_t)b * HW * C_DIM + (size_t)hw0 * C_DIM + c0;

        const int warp = t >> 5;
        const int lane = t & 31;
#pragma unroll
        for (int k = 0; k < 2; k++) {
            const int row = warp + 8 * k;
            const float a  = tile[2 * lane + 0][row];
            const float bb = tile[2 * lane + 1][row];
            ((half2*)(op + (size_t)row * C_DIM))[lane] = __floats2half2_rn(a, bb);
        }
        return;
    }

    // ---------------- 64-px-tile path (lvl2, lvl3) ----------------
    bid -= (S16_LVL0 + S16_LVL1);
    int lvl;
    const float* __restrict__ in;
    size_t base;
    int fbase, tilesPB;
    if (bid < 512) { lvl = 2; in = p2; base = 41943040ul; fbase = 10240; tilesPB = 64; }
    else           { lvl = 3; in = p3; base = 44040192ul; fbase = 10368; tilesPB = 16; bid -= 512; }

    const int Hs = 256 >> lvl;
    const int HW = Hs * Hs;
    const int hwTiles = HW >> 6;

    const int hwTile = bid % hwTiles;
    const int rest   = bid / hwTiles;
    const int cTile  = rest & 3;
    const int b      = rest >> 2;

    if (__ldcg(&g_flags[fbase + b * tilesPB + hwTile]) == 0) return;

    float (*tile)[65] = (float(*)[65])smem_tile;
    const int hw0 = hwTile << 6;
    const int c0  = cTile << 6;

    const int tx = t & 15;
    const int ty = t >> 4;

    const float* __restrict__ ip =
        in + (size_t)b * C_DIM * HW + (size_t)c0 * HW + hw0;

#pragma unroll
    for (int k = 0; k < 4; k++) {
        const int c = ty + 16 * k;
        const float4 v = __ldcs((const float4*)(ip + (size_t)c * HW + 4 * tx));
        tile[c][4 * tx + 0] = v.x;
        tile[c][4 * tx + 1] = v.y;
        tile[c][4 * tx + 2] = v.z;
        tile[c][4 * tx + 3] = v.w;
    }
    __syncthreads();

    __half* __restrict__ op =
        g_nhwc + base + (size_t)b * HW * C_DIM + (size_t)hw0 * C_DIM + c0;

    const int c2 = t & 31;
    const int r0 = t >> 5;
#pragma unroll
    for (int k = 0; k < 8; k++) {
        const int row = r0 + 8 * k;
        const float a  = tile[2 * c2 + 0][row];
        const float bb = tile[2 * c2 + 1][row];
        ((half2*)(op + (size_t)row * C_DIM))[c2] = __floats2half2_rn(a, bb);
    }
}

// -------------------------------------------------------------------------
// ROIAlign gather. Grid (512 rois, 4 chunks); each block does 64 channels.
// 2 bins per warp iteration (doubled MLP). Epilogue re-zeroes flags and the
// marker counter for the next invocation.
// -------------------------------------------------------------------------
__global__ __launch_bounds__(256) void k_gather(const float* __restrict__ boxes,
                                                float* __restrict__ out) {
    __shared__ int4  s_oq[196];
    __shared__ uint4 s_wq[196];
    __shared__ float s_out[NBIN * 66];

    const int tid = threadIdx.x;
    const int roi = blockIdx.x;
    const int c0  = blockIdx.y << 6;
    const int b   = roi >> 8;

    const float bx1 = __ldg(boxes + roi * 4 + 0);
    const float by1 = __ldg(boxes + roi * 4 + 1);
    const float bx2 = __ldg(boxes + roi * 4 + 2);
    const float by2 = __ldg(boxes + roi * 4 + 3);

    int lvl, H; float scale;
    roi_level(bx1, by1, bx2, by2, lvl, H, scale);

    const size_t base_off = ((lvl == 0) ? 0ul
                           : (lvl == 1) ? 33554432ul
                           : (lvl == 2) ? 41943040ul
                           :              44040192ul)
                          + (size_t)b * H * H * C_DIM;
    const __half* __restrict__ fb = g_nhwc + base_off + c0;

    const float x1s = bx1 * scale - 0.5f;
    const float y1s = by1 * scale - 0.5f;
    const float bw  = ((bx2 * scale - 0.5f) - x1s) * (1.0f / 7.0f);
    const float bh  = ((by2 * scale - 0.5f) - y1s) * (1.0f / 7.0f);

    if (tid < 196) {
        const int iy = tid / 14;
        const int ix = tid - iy * 14;
        const float ys = y1s + ((float)iy + 0.5f) * 0.5f * bh;
        const float xs = x1s + ((float)ix + 0.5f) * 0.5f * bw;
        const bool valid = (ys >= -1.0f) && (ys <= (float)H) &&
                           (xs >= -1.0f) && (xs <= (float)H);
        const float yc = fminf(fmaxf(ys, 0.0f), (float)(H - 1));
        const float xc = fminf(fmaxf(xs, 0.0f), (float)(H - 1));
        const int y0  = (int)floorf(yc);
        const int x0  = (int)floorf(xc);
        const int y1i = min(y0 + 1, H - 1);
        const int x1i = min(x0 + 1, H - 1);
        const float ly = yc - (float)y0, hy = 1.0f - ly;
        const float lx = xc - (float)x0, hx = 1.0f - lx;
        const float m = valid ? 0.25f : 0.0f;   // fold 2x2 mean
        const half2 w0 = __float2half2_rn(hy * hx * m);
        const half2 w1 = __float2half2_rn(hy * lx * m);
        const half2 w2 = __float2half2_rn(ly * hx * m);
        const half2 w3 = __float2half2_rn(ly * lx * m);
        uint4 wq;
        wq.x = *(const unsigned int*)&w0;
        wq.y = *(const unsigned int*)&w1;
        wq.z = *(const unsigned int*)&w2;
        wq.w = *(const unsigned int*)&w3;
        s_wq[tid] = wq;
        const int r0 = y0 * H, r1 = y1i * H;
        int4 oq;
        oq.x = (r0 + x0)  * C_DIM;
        oq.y = (r0 + x1i) * C_DIM;
        oq.z = (r1 + x0)  * C_DIM;
        oq.w = (r1 + x1i) * C_DIM;
        s_oq[tid] = oq;
    }
    __syncthreads();

    const int warp = tid >> 5;
    const int lane = tid & 31;
    const int cl   = lane << 1;

#pragma unroll
    for (int j = 0; j < 3; j++) {
        const int binA = 16 * j + warp;
        const int binB = binA + 8;
        half2 v[2][16];
#pragma unroll
        for (int p = 0; p < 2; p++) {
            const int bin = p ? binB : binA;
            const int ph = bin / 7;
            const int pw = bin - ph * 7;
#pragma unroll
            for (int sy = 0; sy < 2; sy++) {
#pragma unroll
                for (int sx = 0; sx < 2; sx++) {
                    const int k = sy * 2 + sx;
                    const int s = (ph * 2 + sy) * 14 + (pw * 2 + sx);
                    const int4 oq = s_oq[s];
                    v[p][k * 4 + 0] = *(const half2*)(fb + oq.x + cl);
                    v[p][k * 4 + 1] = *(const half2*)(fb + oq.y + cl);
                    v[p][k * 4 + 2] = *(const half2*)(fb + oq.z + cl);
                    v[p][k * 4 + 3] = *(const half2*)(fb + oq.w + cl);
                }
            }
        }
#pragma unroll
        for (int p = 0; p < 2; p++) {
            const int bin = p ? binB : binA;
            const int ph = bin / 7;
            const int pw = bin - ph * 7;
            float ax = 0.f, ay = 0.f;
#pragma unroll
            for (int sy = 0; sy < 2; sy++) {
#pragma unroll
                for (int sx = 0; sx < 2; sx++) {
                    const int k = sy * 2 + sx;
                    const int s = (ph * 2 + sy) * 14 + (pw * 2 + sx);
                    const uint4 wq = s_wq[s];
                    half2 acc = __hmul2(*(const half2*)&wq.x, v[p][k * 4 + 0]);
                    acc = __hfma2(*(const half2*)&wq.y, v[p][k * 4 + 1], acc);
                    acc = __hfma2(*(const half2*)&wq.z, v[p][k * 4 + 2], acc);
                    acc = __hfma2(*(const half2*)&wq.w, v[p][k * 4 + 3], acc);
                    const float2 f = __half22float2(acc);
                    ax += f.x;
                    ay += f.y;
                }
            }
            *(float2*)(&s_out[bin * 66 + cl]) = make_float2(ax, ay);
        }
    }

    if (warp == 0) {   // tail bin 48
        const int bin = 48;
        float ax = 0.f, ay = 0.f;
#pragma unroll
        for (int sy = 0; sy < 2; sy++) {
#pragma unroll
            for (int sx = 0; sx < 2; sx++) {
                const int s = (12 + sy) * 14 + (12 + sx);
                const uint4 wq = s_wq[s];
                const int4  oq = s_oq[s];
                half2 acc = __hmul2(*(const half2*)&wq.x, *(const half2*)(fb + oq.x + cl));
                acc = __hfma2(*(const half2*)&wq.y, *(const half2*)(fb + oq.y + cl), acc);
                acc = __hfma2(*(const half2*)&wq.z, *(const half2*)(fb + oq.z + cl), acc);
                acc = __hfma2(*(const half2*)&wq.w, *(const half2*)(fb + oq.w + cl), acc);
                const float2 f = __half22float2(acc);
                ax += f.x;
                ay += f.y;
            }
        }
        *(float2*)(&s_out[bin * 66 + cl]) = make_float2(ax, ay);
    }
    __syncthreads();

    float* __restrict__ og = out + (size_t)roi * (C_DIM * NBIN) + (size_t)c0 * NBIN;
    for (int e = tid; e < 64 * NBIN; e += 256) {
        const int ch  = e / NBIN;
        const int bin = e - ch * NBIN;
        og[e] = s_out[bin * 66 + ch];
    }

    // Epilogue: re-zero flags + marker counter for the next invocation.
    if (blockIdx.y == 0) {
        const int gid = roi * 256 + tid;
        if (gid < NFLAGS) g_flags[gid] = 0;
        if (gid == 0) g_mark_done = 0;
    }
}

// -------------------------------------------------------------------------
extern "C" void kernel_launch(void* const* d_in, const int* in_sizes, int n_in,
                              void* d_out, int out_size) {
    const float* x2 = (const float*)d_in[0];   // [2,256,256,256]
    const float* x3 = (const float*)d_in[1];   // [2,256,128,128]
    const float* x4 = (const float*)d_in[2];   // [2,256, 64, 64]
    const float* x5 = (const float*)d_in[3];   // [2,256, 32, 32]
    const float* boxes = (const float*)d_in[4];// [2,256,4]
    float* out = (float*)d_out;                // [512,256,7,7]

    k_fused<<<T_ALL, 256>>>(x2, x3, x4, x5, boxes);
    dim3 ggrid(NROI, 4);
    k_gather<<<ggrid, 256>>>(boxes, out);
}

// round 16
// speedup vs baseline: 1.4534x; 1.4534x over previous
#include <cuda_runtime.h>
#include <cuda_fp16.h>
#include <math.h>

#define C_DIM 256
#define NROI  512
#define NBIN  49

// NHWC fp16 scratch, 4 levels (element offsets):
// lvl0 base 0 (2*256*256*256), lvl1 base 33554432, lvl2 base 41943040, lvl3 base 44040192
__device__ __half g_nhwc[44564480];

// Per-tile "needed" flags.
// lvl0: 16-px tiles -> 4096/batch, [0, 8192)
// lvl1: 16-px tiles -> 1024/batch, [8192, 10240)
// lvl2: 64-px tiles -> 64/batch,   [10240, 10368)
// lvl3: 64-px tiles -> 16/batch,   [10368, 10400)
// Zero-initialized at load; re-zeroed by k_gather's epilogue each call.
#define NFLAGS 10400
__device__ unsigned char g_flags[NFLAGS];

#define S16_LVL0 32768           // 2b * 4c * 4096
#define S16_LVL1 8192            // 2b * 4c * 1024
#define S64_BLOCKS 640           // lvl2 512 + lvl3 128
#define T_ALL (S16_LVL0 + S16_LVL1 + S64_BLOCKS)   // 41600

__device__ __forceinline__ void roi_level(float bx1, float by1, float bx2, float by2,
                                          int& lvl, int& H, float& scale) {
    const float size = sqrtf((bx2 - bx1) * (by2 - by1));
    int l = (int)floorf(4.0f + log2f(size / 224.0f + 1e-8f));
    lvl = max(2, min(5, l)) - 2;
    H = 256 >> lvl;
    scale = 0.25f / (float)(1 << lvl);
}

// -------------------------------------------------------------------------
// Marker: one block per ROI (64 threads); thread = feature row.
// lvl0/lvl1 mark 16-px tiles; lvl2/lvl3 mark 64-px tiles.
// Flags arrive zeroed (initial load / previous call's gather epilogue).
// -------------------------------------------------------------------------
__global__ __launch_bounds__(64) void k_mark(const float* __restrict__ boxes) {
    const int roi = blockIdx.x;
    const int b   = roi >> 8;
    const float bx1 = __ldg(boxes + roi * 4 + 0);
    const float by1 = __ldg(boxes + roi * 4 + 1);
    const float bx2 = __ldg(boxes + roi * 4 + 2);
    const float by2 = __ldg(boxes + roi * 4 + 3);

    int lvl, H; float scale;
    roi_level(bx1, by1, bx2, by2, lvl, H, scale);

    const float x1s = bx1 * scale - 0.5f;
    const float y1s = by1 * scale - 0.5f;
    const float x2s = bx2 * scale - 0.5f;
    const float y2s = by2 * scale - 0.5f;

    const float Hm1 = (float)(H - 1);
    const int xa = (int)floorf(fminf(fmaxf(x1s, 0.0f), Hm1));
    const int xb = min((int)floorf(fminf(fmaxf(x2s, 0.0f), Hm1)) + 1, H - 1);
    const int ya = (int)floorf(fminf(fmaxf(y1s, 0.0f), Hm1));
    const int yb = min((int)floorf(fminf(fmaxf(y2s, 0.0f), Hm1)) + 1, H - 1);

    const int fbase   = (lvl == 0) ? 0 : (lvl == 1) ? 8192 : (lvl == 2) ? 10240 : 10368;
    const int tilesPB = (lvl == 0) ? 4096 : (lvl == 1) ? 1024 : (lvl == 2) ? 64 : 16;
    const int sh      = (lvl <= 1) ? 4 : 6;
    unsigned char* fl = g_flags + fbase + b * tilesPB;

    for (int y = ya + (int)threadIdx.x; y <= yb; y += 64) {
        const int t0 = (y * H + xa) >> sh;
        const int t1 = (y * H + xb) >> sh;
        for (int t = t0; t <= t1; t++) fl[t] = 1;
    }
}

// -------------------------------------------------------------------------
// Combined NCHW -> NHWC(fp16) transpose, all 4 levels, ONE launch.
// Blocks [0, 32768): lvl0 64c x 16hw tiles.
// Blocks [32768, 40960): lvl1 64c x 16hw tiles.
// Blocks [40960, 41600): lvl2/lvl3 64c x 64hw tiles.
// -------------------------------------------------------------------------
__global__ __launch_bounds__(256) void k_transpose(const float* __restrict__ p0,
                                                   const float* __restrict__ p1,
                                                   const float* __restrict__ p2,
                                                   const float* __restrict__ p3) {
    __shared__ float smem_tile[64 * 65];   // union: 16hw path uses 64*17
    const int t = threadIdx.x;
    int bid = blockIdx.x;

    if (bid < S16_LVL0 + S16_LVL1) {
        // ---------------- 16-px-tile path (lvl0, lvl1) ----------------
        int HW, hwTile, cTile, b, fbase, tilesPB;
        const float* __restrict__ in;
        size_t base;
        if (bid < S16_LVL0) {
            in = p0; base = 0ul; fbase = 0; HW = 65536; tilesPB = 4096;
            hwTile = bid & 4095; cTile = (bid >> 12) & 3; b = bid >> 14;
        } else {
            bid -= S16_LVL0;
            in = p1; base = 33554432ul; fbase = 8192; HW = 16384; tilesPB = 1024;
            hwTile = bid & 1023; cTile = (bid >> 10) & 3; b = bid >> 12;
        }
        if (g_flags[fbase + b * tilesPB + hwTile] == 0) return;

        float (*tile)[17] = (float(*)[17])smem_tile;
        const int hw0 = hwTile << 4;
        const int c0  = cTile << 6;

        const int c = t >> 2;
        const int g = t & 3;

        const float* __restrict__ ip =
            in + (size_t)b * C_DIM * HW + (size_t)(c0 + c) * HW + hw0 + 4 * g;
        const float4 v = __ldcs((const float4*)ip);
        tile[c][4 * g + 0] = v.x;
        tile[c][4 * g + 1] = v.y;
        tile[c][4 * g + 2] = v.z;
        tile[c][4 * g + 3] = v.w;
        __syncthreads();

        __half* __restrict__ op =
            g_nhwc + base + (size_t)b * HW * C_DIM + (size_t)hw0 * C_DIM + c0;

        const int warp = t >> 5;
        const int lane = t & 31;
#pragma unroll
        for (int k = 0; k < 2; k++) {
            const int row = warp + 8 * k;
            const float a  = tile[2 * lane + 0][row];
            const float bb = tile[2 * lane + 1][row];
            ((half2*)(op + (size_t)row * C_DIM))[lane] = __floats2half2_rn(a, bb);
        }
        return;
    }

    // ---------------- 64-px-tile path (lvl2, lvl3) ----------------
    bid -= (S16_LVL0 + S16_LVL1);
    int lvl;
    const float* __restrict__ in;
    size_t base;
    int fbase, tilesPB;
    if (bid < 512) { lvl = 2; in = p2; base = 41943040ul; fbase = 10240; tilesPB = 64; }
    else           { lvl = 3; in = p3; base = 44040192ul; fbase = 10368; tilesPB = 16; bid -= 512; }

    const int Hs = 256 >> lvl;
    const int HW = Hs * Hs;
    const int hwTiles = HW >> 6;

    const int hwTile = bid % hwTiles;
    const int rest   = bid / hwTiles;
    const int cTile  = rest & 3;
    const int b      = rest >> 2;

    if (g_flags[fbase + b * tilesPB + hwTile] == 0) return;

    float (*tile)[65] = (float(*)[65])smem_tile;
    const int hw0 = hwTile << 6;
    const int c0  = cTile << 6;

    const int tx = t & 15;
    const int ty = t >> 4;

    const float* __restrict__ ip =
        in + (size_t)b * C_DIM * HW + (size_t)c0 * HW + hw0;

#pragma unroll
    for (int k = 0; k < 4; k++) {
        const int c = ty + 16 * k;
        const float4 v = __ldcs((const float4*)(ip + (size_t)c * HW + 4 * tx));
        tile[c][4 * tx + 0] = v.x;
        tile[c][4 * tx + 1] = v.y;
        tile[c][4 * tx + 2] = v.z;
        tile[c][4 * tx + 3] = v.w;
    }
    __syncthreads();

    __half* __restrict__ op =
        g_nhwc + base + (size_t)b * HW * C_DIM + (size_t)hw0 * C_DIM + c0;

    const int c2 = t & 31;
    const int r0 = t >> 5;
#pragma unroll
    for (int k = 0; k < 8; k++) {
        const int row = r0 + 8 * k;
        const float a  = tile[2 * c2 + 0][row];
        const float bb = tile[2 * c2 + 1][row];
        ((half2*)(op + (size_t)row * C_DIM))[c2] = __floats2half2_rn(a, bb);
    }
}

// -------------------------------------------------------------------------
// ROIAlign gather. Grid (512 rois, 4 chunks); each block does 64 channels.
// 2 bins per warp iteration (doubled MLP). Epilogue re-zeroes flags for the
// next invocation.
// -------------------------------------------------------------------------
__global__ __launch_bounds__(256) void k_gather(const float* __restrict__ boxes,
                                                float* __restrict__ out) {
    __shared__ int4  s_oq[196];
    __shared__ uint4 s_wq[196];
    __shared__ float s_out[NBIN * 66];

    const int tid = threadIdx.x;
    const int roi = blockIdx.x;
    const int c0  = blockIdx.y << 6;
    const int b   = roi >> 8;

    const float bx1 = __ldg(boxes + roi * 4 + 0);
    const float by1 = __ldg(boxes + roi * 4 + 1);
    const float bx2 = __ldg(boxes + roi * 4 + 2);
    const float by2 = __ldg(boxes + roi * 4 + 3);

    int lvl, H; float scale;
    roi_level(bx1, by1, bx2, by2, lvl, H, scale);

    const size_t base_off = ((lvl == 0) ? 0ul
                           : (lvl == 1) ? 33554432ul
                           : (lvl == 2) ? 41943040ul
                           :              44040192ul)
                          + (size_t)b * H * H * C_DIM;
    const __half* __restrict__ fb = g_nhwc + base_off + c0;

    const float x1s = bx1 * scale - 0.5f;
    const float y1s = by1 * scale - 0.5f;
    const float bw  = ((bx2 * scale - 0.5f) - x1s) * (1.0f / 7.0f);
    const float bh  = ((by2 * scale - 0.5f) - y1s) * (1.0f / 7.0f);

    if (tid < 196) {
        const int iy = tid / 14;
        const int ix = tid - iy * 14;
        const float ys = y1s + ((float)iy + 0.5f) * 0.5f * bh;
        const float xs = x1s + ((float)ix + 0.5f) * 0.5f * bw;
        const bool valid = (ys >= -1.0f) && (ys <= (float)H) &&
                           (xs >= -1.0f) && (xs <= (float)H);
        const float yc = fminf(fmaxf(ys, 0.0f), (float)(H - 1));
        const float xc = fminf(fmaxf(xs, 0.0f), (float)(H - 1));
        const int y0  = (int)floorf(yc);
        const int x0  = (int)floorf(xc);
        const int y1i = min(y0 + 1, H - 1);
        const int x1i = min(x0 + 1, H - 1);
        const float ly = yc - (float)y0, hy = 1.0f - ly;
        const float lx = xc - (float)x0, hx = 1.0f - lx;
        const float m = valid ? 0.25f : 0.0f;   // fold 2x2 mean
        const half2 w0 = __float2half2_rn(hy * hx * m);
        const half2 w1 = __float2half2_rn(hy * lx * m);
        const half2 w2 = __float2half2_rn(ly * hx * m);
        const half2 w3 = __float2half2_rn(ly * lx * m);
        uint4 wq;
        wq.x = *(const unsigned int*)&w0;
        wq.y = *(const unsigned int*)&w1;
        wq.z = *(const unsigned int*)&w2;
        wq.w = *(const unsigned int*)&w3;
        s_wq[tid] = wq;
        const int r0 = y0 * H, r1 = y1i * H;
        int4 oq;
        oq.x = (r0 + x0)  * C_DIM;
        oq.y = (r0 + x1i) * C_DIM;
        oq.z = (r1 + x0)  * C_DIM;
        oq.w = (r1 + x1i) * C_DIM;
        s_oq[tid] = oq;
    }
    __syncthreads();

    const int warp = tid >> 5;
    const int lane = tid & 31;
    const int cl   = lane << 1;

#pragma unroll
    for (int j = 0; j < 3; j++) {
        const int binA = 16 * j + warp;
        const int binB = binA + 8;
        half2 v[2][16];
#pragma unroll
        for (int p = 0; p < 2; p++) {
            const int bin = p ? binB : binA;
            const int ph = bin / 7;
            const int pw = bin - ph * 7;
#pragma unroll
            for (int sy = 0; sy < 2; sy++) {
#pragma unroll
                for (int sx = 0; sx < 2; sx++) {
                    const int k = sy * 2 + sx;
                    const int s = (ph * 2 + sy) * 14 + (pw * 2 + sx);
                    const int4 oq = s_oq[s];
                    v[p][k * 4 + 0] = *(const half2*)(fb + oq.x + cl);
                    v[p][k * 4 + 1] = *(const half2*)(fb + oq.y + cl);
                    v[p][k * 4 + 2] = *(const half2*)(fb + oq.z + cl);
                    v[p][k * 4 + 3] = *(const half2*)(fb + oq.w + cl);
                }
            }
        }
#pragma unroll
        for (int p = 0; p < 2; p++) {
            const int bin = p ? binB : binA;
            const int ph = bin / 7;
            const int pw = bin - ph * 7;
            float ax = 0.f, ay = 0.f;
#pragma unroll
            for (int sy = 0; sy < 2; sy++) {
#pragma unroll
                for (int sx = 0; sx < 2; sx++) {
                    const int k = sy * 2 + sx;
                    const int s = (ph * 2 + sy) * 14 + (pw * 2 + sx);
                    const uint4 wq = s_wq[s];
                    half2 acc = __hmul2(*(const half2*)&wq.x, v[p][k * 4 + 0]);
                    acc = __hfma2(*(const half2*)&wq.y, v[p][k * 4 + 1], acc);
                    acc = __hfma2(*(const half2*)&wq.z, v[p][k * 4 + 2], acc);
                    acc = __hfma2(*(const half2*)&wq.w, v[p][k * 4 + 3], acc);
                    const float2 f = __half22float2(acc);
                    ax += f.x;
                    ay += f.y;
                }
            }
            *(float2*)(&s_out[bin * 66 + cl]) = make_float2(ax, ay);
        }
    }

    if (warp == 0) {   // tail bin 48
        const int bin = 48;
        float ax = 0.f, ay = 0.f;
#pragma unroll
        for (int sy = 0; sy < 2; sy++) {
#pragma unroll
            for (int sx = 0; sx < 2; sx++) {
                const int s = (12 + sy) * 14 + (12 + sx);
                const uint4 wq = s_wq[s];
                const int4  oq = s_oq[s];
                half2 acc = __hmul2(*(const half2*)&wq.x, *(const half2*)(fb + oq.x + cl));
                acc = __hfma2(*(const half2*)&wq.y, *(const half2*)(fb + oq.y + cl), acc);
                acc = __hfma2(*(const half2*)&wq.z, *(const half2*)(fb + oq.z + cl), acc);
                acc = __hfma2(*(const half2*)&wq.w, *(const half2*)(fb + oq.w + cl), acc);
                const float2 f = __half22float2(acc);
                ax += f.x;
                ay += f.y;
            }
        }
        *(float2*)(&s_out[bin * 66 + cl]) = make_float2(ax, ay);
    }
    __syncthreads();

    float* __restrict__ og = out + (size_t)roi * (C_DIM * NBIN) + (size_t)c0 * NBIN;
    for (int e = tid; e < 64 * NBIN; e += 256) {
        const int ch  = e / NBIN;
        const int bin = e - ch * NBIN;
        og[e] = s_out[bin * 66 + ch];
    }

    // Epilogue: re-zero flags for the next invocation.
    if (blockIdx.y == 0) {
        const int gid = roi * 256 + tid;
        if (gid < NFLAGS) g_flags[gid] = 0;
    }
}

// -------------------------------------------------------------------------
extern "C" void kernel_launch(void* const* d_in, const int* in_sizes, int n_in,
                              void* d_out, int out_size) {
    const float* x2 = (const float*)d_in[0];   // [2,256,256,256]
    const float* x3 = (const float*)d_in[1];   // [2,256,128,128]
    const float* x4 = (const float*)d_in[2];   // [2,256, 64, 64]
    const float* x5 = (const float*)d_in[3];   // [2,256, 32, 32]
    const float* boxes = (const float*)d_in[4];// [2,256,4]
    float* out = (float*)d_out;                // [512,256,7,7]

    k_mark<<<NROI, 64>>>(boxes);
    k_transpose<<<T_ALL, 256>>>(x2, x3, x4, x5);
    dim3 ggrid(NROI, 4);
    k_gather<<<ggrid, 256>>>(boxes, out);
}

// round 17
// speedup vs baseline: 1.7259x; 1.1875x over previous
#include <cuda_runtime.h>
#include <cuda_fp16.h>
#include <math.h>

#define C_DIM 256
#define NROI  512
#define NBIN  49

// NHWC fp16 scratch, 4 levels (element offsets):
// lvl0 base 0 (2*256*256*256), lvl1 base 33554432, lvl2 base 41943040, lvl3 base 44040192
__device__ __half g_nhwc[44564480];

// Per-tile "needed" flags (round-13 layout).
// lvl0: 16-px tiles -> 4096/batch, [0, 8192)
// lvl1: 64-px tiles -> 256/batch,  [8192, 8704)
// lvl2: 64-px tiles -> 64/batch,   [8704, 8832)
// lvl3: 64-px tiles -> 16/batch,   [8832, 8864)
// Zero-initialized at load; re-zeroed by k_gather's epilogue each call.
#define NFLAGS 8864
__device__ unsigned char g_flags[NFLAGS];

#define T0_BLOCKS 8192            // 2b * 4096 hw-tiles (ALL 256 channels/block)
#define T123_BLOCKS 2688          // lvl1 2048, lvl2 512, lvl3 128
#define T_ALL (T0_BLOCKS + T123_BLOCKS)   // 10880

__device__ __forceinline__ void roi_level(float bx1, float by1, float bx2, float by2,
                                          int& lvl, int& H, float& scale) {
    const float size = sqrtf((bx2 - bx1) * (by2 - by1));
    int l = (int)floorf(4.0f + log2f(size / 224.0f + 1e-8f));
    lvl = max(2, min(5, l)) - 2;
    H = 256 >> lvl;
    scale = 0.25f / (float)(1 << lvl);
}

// -------------------------------------------------------------------------
// Marker: 4 ROIs per 256-thread block (128 blocks); 64 threads per ROI,
// thread = feature row. Flags arrive zeroed.
// -------------------------------------------------------------------------
__global__ __launch_bounds__(256) void k_mark(const float* __restrict__ boxes) {
    const int tid  = threadIdx.x;
    const int roi  = blockIdx.x * 4 + (tid >> 6);
    const int lt   = tid & 63;
    const int b    = roi >> 8;

    const float bx1 = __ldg(boxes + roi * 4 + 0);
    const float by1 = __ldg(boxes + roi * 4 + 1);
    const float bx2 = __ldg(boxes + roi * 4 + 2);
    const float by2 = __ldg(boxes + roi * 4 + 3);

    int lvl, H; float scale;
    roi_level(bx1, by1, bx2, by2, lvl, H, scale);

    const float x1s = bx1 * scale - 0.5f;
    const float y1s = by1 * scale - 0.5f;
    const float x2s = bx2 * scale - 0.5f;
    const float y2s = by2 * scale - 0.5f;

    const float Hm1 = (float)(H - 1);
    const int xa = (int)floorf(fminf(fmaxf(x1s, 0.0f), Hm1));
    const int xb = min((int)floorf(fminf(fmaxf(x2s, 0.0f), Hm1)) + 1, H - 1);
    const int ya = (int)floorf(fminf(fmaxf(y1s, 0.0f), Hm1));
    const int yb = min((int)floorf(fminf(fmaxf(y2s, 0.0f), Hm1)) + 1, H - 1);

    const int fbase   = (lvl == 0) ? 0 : (lvl == 1) ? 8192 : (lvl == 2) ? 8704 : 8832;
    const int tilesPB = (lvl == 0) ? 4096 : (lvl == 1) ? 256 : (lvl == 2) ? 64 : 16;
    const int sh      = (lvl == 0) ? 4 : 6;
    unsigned char* fl = g_flags + fbase + b * tilesPB;

    for (int y = ya + lt; y <= yb; y += 64) {
        const int t0 = (y * H + xa) >> sh;
        const int t1 = (y * H + xb) >> sh;
        for (int t = t0; t <= t1; t++) fl[t] = 1;
    }
}

// -------------------------------------------------------------------------
// Combined NCHW -> NHWC(fp16) transpose, all 4 levels, ONE launch.
// Blocks [0, 8192): lvl0 — 16hw x 256c per block (4 float4 loads/thread,
//                   MLP=4; skip at 16-px granularity).
// Blocks [8192, 10880): lvl1-3 — 64c x 64hw tiles (64-px granularity).
// -------------------------------------------------------------------------
__global__ __launch_bounds__(256) void k_transpose(const float* __restrict__ p0,
                                                   const float* __restrict__ p1,
                                                   const float* __restrict__ p2,
                                                   const float* __restrict__ p3) {
    __shared__ float smem_tile[256 * 17];   // 17408B; lvl1-3 path uses 64*65=16640B
    const int t = threadIdx.x;

    if (blockIdx.x < T0_BLOCKS) {
        // ---------------- lvl0: 16hw x 256c ----------------
        const int bid    = blockIdx.x;
        const int hwTile = bid & 4095;
        const int b      = bid >> 12;

        if (g_flags[b * 4096 + hwTile] == 0) return;

        float (*tile)[17] = (float(*)[17])smem_tile;
        const int HW  = 65536;
        const int hw0 = hwTile << 4;

        const int cg = t >> 2;    // channel within 64-group
        const int g  = t & 3;     // float4 group within 16 hw

        const float* __restrict__ ip =
            p0 + (size_t)b * C_DIM * HW + hw0 + 4 * g;
#pragma unroll
        for (int k = 0; k < 4; k++) {
            const int c = cg + 64 * k;
            const float4 v = __ldcs((const float4*)(ip + (size_t)c * HW));
            tile[c][4 * g + 0] = v.x;
            tile[c][4 * g + 1] = v.y;
            tile[c][4 * g + 2] = v.z;
            tile[c][4 * g + 3] = v.w;
        }
        __syncthreads();

        __half* __restrict__ op =
            g_nhwc + (size_t)b * HW * C_DIM + (size_t)hw0 * C_DIM;

        const int warp = t >> 5;
        const int lane = t & 31;
#pragma unroll
        for (int k = 0; k < 2; k++) {
            const int row = warp + 8 * k;
            __half* __restrict__ orow = op + (size_t)row * C_DIM;
#pragma unroll
            for (int j = 0; j < 4; j++) {
                const int ch2 = lane + 32 * j;            // half2 index 0..127
                const float a  = tile[2 * ch2 + 0][row];
                const float bb = tile[2 * ch2 + 1][row];
                ((half2*)orow)[ch2] = __floats2half2_rn(a, bb);
            }
        }
        return;
    }

    // ---------------- lvl1-3: 64c x 64hw ----------------
    int bid = blockIdx.x - T0_BLOCKS;
    int lvl;
    const float* __restrict__ in;
    size_t base;
    int fbase, tilesPB;
    if (bid < 2048)      { lvl = 1; in = p1; base = 33554432ul; fbase = 8192; tilesPB = 256; }
    else if (bid < 2560) { lvl = 2; in = p2; base = 41943040ul; fbase = 8704; tilesPB = 64;  bid -= 2048; }
    else                 { lvl = 3; in = p3; base = 44040192ul; fbase = 8832; tilesPB = 16;  bid -= 2560; }

    const int Hs = 256 >> lvl;
    const int HW = Hs * Hs;
    const int hwTiles = HW >> 6;

    const int hwTile = bid % hwTiles;
    const int rest   = bid / hwTiles;
    const int cTile  = rest & 3;
    const int b      = rest >> 2;

    if (g_flags[fbase + b * tilesPB + hwTile] == 0) return;

    float (*tile)[65] = (float(*)[65])smem_tile;
    const int hw0 = hwTile << 6;
    const int c0  = cTile << 6;

    const int tx = t & 15;
    const int ty = t >> 4;

    const float* __restrict__ ip =
        in + (size_t)b * C_DIM * HW + (size_t)c0 * HW + hw0;

#pragma unroll
    for (int k = 0; k < 4; k++) {
        const int c = ty + 16 * k;
        const float4 v = __ldcs((const float4*)(ip + (size_t)c * HW + 4 * tx));
        tile[c][4 * tx + 0] = v.x;
        tile[c][4 * tx + 1] = v.y;
        tile[c][4 * tx + 2] = v.z;
        tile[c][4 * tx + 3] = v.w;
    }
    __syncthreads();

    __half* __restrict__ op =
        g_nhwc + base + (size_t)b * HW * C_DIM + (size_t)hw0 * C_DIM + c0;

    const int c2 = t & 31;
    const int r0 = t >> 5;
#pragma unroll
    for (int k = 0; k < 8; k++) {
        const int row = r0 + 8 * k;
        const float a  = tile[2 * c2 + 0][row];
        const float bb = tile[2 * c2 + 1][row];
        ((half2*)(op + (size_t)row * C_DIM))[c2] = __floats2half2_rn(a, bb);
    }
}

// -------------------------------------------------------------------------
// ROIAlign gather (round-13 config). Grid (512 rois, 4 chunks); 64 ch/block.
// 2 bins per warp iteration (doubled MLP). Epilogue re-zeroes flags.
// -------------------------------------------------------------------------
__global__ __launch_bounds__(256) void k_gather(const float* __restrict__ boxes,
                                                float* __restrict__ out) {
    __shared__ int4  s_oq[196];
    __shared__ uint4 s_wq[196];
    __shared__ float s_out[NBIN * 66];

    const int tid = threadIdx.x;
    const int roi = blockIdx.x;
    const int c0  = blockIdx.y << 6;
    const int b   = roi >> 8;

    const float bx1 = __ldg(boxes + roi * 4 + 0);
    const float by1 = __ldg(boxes + roi * 4 + 1);
    const float bx2 = __ldg(boxes + roi * 4 + 2);
    const float by2 = __ldg(boxes + roi * 4 + 3);

    int lvl, H; float scale;
    roi_level(bx1, by1, bx2, by2, lvl, H, scale);

    const size_t base_off = ((lvl == 0) ? 0ul
                           : (lvl == 1) ? 33554432ul
                           : (lvl == 2) ? 41943040ul
                           :              44040192ul)
                          + (size_t)b * H * H * C_DIM;
    const __half* __restrict__ fb = g_nhwc + base_off + c0;

    const float x1s = bx1 * scale - 0.5f;
    const float y1s = by1 * scale - 0.5f;
    const float bw  = ((bx2 * scale - 0.5f) - x1s) * (1.0f / 7.0f);
    const float bh  = ((by2 * scale - 0.5f) - y1s) * (1.0f / 7.0f);

    if (tid < 196) {
        const int iy = tid / 14;
        const int ix = tid - iy * 14;
        const float ys = y1s + ((float)iy + 0.5f) * 0.5f * bh;
        const float xs = x1s + ((float)ix + 0.5f) * 0.5f * bw;
        const bool valid = (ys >= -1.0f) && (ys <= (float)H) &&
                           (xs >= -1.0f) && (xs <= (float)H);
        const float yc = fminf(fmaxf(ys, 0.0f), (float)(H - 1));
        const float xc = fminf(fmaxf(xs, 0.0f), (float)(H - 1));
        const int y0  = (int)floorf(yc);
        const int x0  = (int)floorf(xc);
        const int y1i = min(y0 + 1, H - 1);
        const int x1i = min(x0 + 1, H - 1);
        const float ly = yc - (float)y0, hy = 1.0f - ly;
        const float lx = xc - (float)x0, hx = 1.0f - lx;
        const float m = valid ? 0.25f : 0.0f;   // fold 2x2 mean
        const half2 w0 = __float2half2_rn(hy * hx * m);
        const half2 w1 = __float2half2_rn(hy * lx * m);
        const half2 w2 = __float2half2_rn(ly * hx * m);
        const half2 w3 = __float2half2_rn(ly * lx * m);
        uint4 wq;
        wq.x = *(const unsigned int*)&w0;
        wq.y = *(const unsigned int*)&w1;
        wq.z = *(const unsigned int*)&w2;
        wq.w = *(const unsigned int*)&w3;
        s_wq[tid] = wq;
        const int r0 = y0 * H, r1 = y1i * H;
        int4 oq;
        oq.x = (r0 + x0)  * C_DIM;
        oq.y = (r0 + x1i) * C_DIM;
        oq.z = (r1 + x0)  * C_DIM;
        oq.w = (r1 + x1i) * C_DIM;
        s_oq[tid] = oq;
    }
    __syncthreads();

    const int warp = tid >> 5;
    const int lane = tid & 31;
    const int cl   = lane << 1;

#pragma unroll
    for (int j = 0; j < 3; j++) {
        const int binA = 16 * j + warp;
        const int binB = binA + 8;
        half2 v[2][16];
#pragma unroll
        for (int p = 0; p < 2; p++) {
            const int bin = p ? binB : binA;
            const int ph = bin / 7;
            const int pw = bin - ph * 7;
#pragma unroll
            for (int sy = 0; sy < 2; sy++) {
#pragma unroll
                for (int sx = 0; sx < 2; sx++) {
                    const int k = sy * 2 + sx;
                    const int s = (ph * 2 + sy) * 14 + (pw * 2 + sx);
                    const int4 oq = s_oq[s];
                    v[p][k * 4 + 0] = *(const half2*)(fb + oq.x + cl);
                    v[p][k * 4 + 1] = *(const half2*)(fb + oq.y + cl);
                    v[p][k * 4 + 2] = *(const half2*)(fb + oq.z + cl);
                    v[p][k * 4 + 3] = *(const half2*)(fb + oq.w + cl);
                }
            }
        }
#pragma unroll
        for (int p = 0; p < 2; p++) {
            const int bin = p ? binB : binA;
            const int ph = bin / 7;
            const int pw = bin - ph * 7;
            float ax = 0.f, ay = 0.f;
#pragma unroll
            for (int sy = 0; sy < 2; sy++) {
#pragma unroll
                for (int sx = 0; sx < 2; sx++) {
                    const int k = sy * 2 + sx;
                    const int s = (ph * 2 + sy) * 14 + (pw * 2 + sx);
                    const uint4 wq = s_wq[s];
                    half2 acc = __hmul2(*(const half2*)&wq.x, v[p][k * 4 + 0]);
                    acc = __hfma2(*(const half2*)&wq.y, v[p][k * 4 + 1], acc);
                    acc = __hfma2(*(const half2*)&wq.z, v[p][k * 4 + 2], acc);
                    acc = __hfma2(*(const half2*)&wq.w, v[p][k * 4 + 3], acc);
                    const float2 f = __half22float2(acc);
                    ax += f.x;
                    ay += f.y;
                }
            }
            *(float2*)(&s_out[bin * 66 + cl]) = make_float2(ax, ay);
        }
    }

    if (warp == 0) {   // tail bin 48
        const int bin = 48;
        float ax = 0.f, ay = 0.f;
#pragma unroll
        for (int sy = 0; sy < 2; sy++) {
#pragma unroll
            for (int sx = 0; sx < 2; sx++) {
                const int s = (12 + sy) * 14 + (12 + sx);
                const uint4 wq = s_wq[s];
                const int4  oq = s_oq[s];
                half2 acc = __hmul2(*(const half2*)&wq.x, *(const half2*)(fb + oq.x + cl));
                acc = __hfma2(*(const half2*)&wq.y, *(const half2*)(fb + oq.y + cl), acc);
                acc = __hfma2(*(const half2*)&wq.z, *(const half2*)(fb + oq.z + cl), acc);
                acc = __hfma2(*(const half2*)&wq.w, *(const half2*)(fb + oq.w + cl), acc);
                const float2 f = __half22float2(acc);
                ax += f.x;
                ay += f.y;
            }
        }
        *(float2*)(&s_out[bin * 66 + cl]) = make_float2(ax, ay);
    }
    __syncthreads();

    float* __restrict__ og = out + (size_t)roi * (C_DIM * NBIN) + (size_t)c0 * NBIN;
    for (int e = tid; e < 64 * NBIN; e += 256) {
        const int ch  = e / NBIN;
        const int bin = e - ch * NBIN;
        og[e] = s_out[bin * 66 + ch];
    }

    // Epilogue: re-zero flags for the next invocation.
    if (blockIdx.y == 0) {
        const int gid = roi * 256 + tid;
        if (gid < NFLAGS) g_flags[gid] = 0;
    }
}

// -------------------------------------------------------------------------
extern "C" void kernel_launch(void* const* d_in, const int* in_sizes, int n_in,
                              void* d_out, int out_size) {
    const float* x2 = (const float*)d_in[0];   // [2,256,256,256]
    const float* x3 = (const float*)d_in[1];   // [2,256,128,128]
    const float* x4 = (const float*)d_in[2];   // [2,256, 64, 64]
    const float* x5 = (const float*)d_in[3];   // [2,256, 32, 32]
    const float* boxes = (const float*)d_in[4];// [2,256,4]
    float* out = (float*)d_out;                // [512,256,7,7]

    k_mark<<<128, 256>>>(boxes);
    k_transpose<<<T_ALL, 256>>>(x2, x3, x4, x5);
    dim3 ggrid(NROI, 4);
    k_gather<<<ggrid, 256>>>(boxes, out);
}